// round 5
// baseline (speedup 1.0000x reference)
#include <cuda_runtime.h>

#define C_DIM 4096
#define N_F 8
#define NPAIR 36            // 8*9/2, i<=j
#define EPS_F 1e-8f
#define NTILE 32            // 4096 / 128
#define NCROSS 528          // NTILE*(NTILE+1)/2 triangle tiles
#define NROWB 256           // 8 factors * 32 u-tiles of 128
#define NBLOCKS (NCROSS + NROWB)

typedef unsigned long long u64;

// Scratch (device globals; no allocation allowed).
__device__ float g_rowsum[N_F * C_DIM];      // rowsum[f][u] = sum_v |x_fu - x_fv|
__device__ float g_parts[NCROSS][NPAIR];     // per-tile cross partials
__device__ unsigned int g_ctr = 0;           // completion ticket (reset by last block)

// ---- packed f32x2 helpers (sm_103a) ----
__device__ __forceinline__ u64 pack2(float lo, float hi) {
    u64 r; asm("mov.b64 %0, {%1, %2};" : "=l"(r) : "f"(lo), "f"(hi)); return r;
}
__device__ __forceinline__ void unpack2(float& lo, float& hi, u64 v) {
    asm("mov.b64 {%0, %1}, %2;" : "=f"(lo), "=f"(hi) : "l"(v));
}
__device__ __forceinline__ u64 add2(u64 a, u64 b) {
    u64 d; asm("add.rn.f32x2 %0, %1, %2;" : "=l"(d) : "l"(a), "l"(b)); return d;
}
__device__ __forceinline__ u64 fma2(u64 a, u64 b, u64 c) {
    u64 d; asm("fma.rn.f32x2 %0, %1, %2, %3;" : "=l"(d) : "l"(a), "l"(b), "l"(c)); return d;
}
__device__ __forceinline__ u64 abs2(u64 a) {
    u64 d; asm("and.b64 %0, %1, 0x7FFFFFFF7FFFFFFF;" : "=l"(d) : "l"(a)); return d;
}

// Single fused kernel. Roles by bid (rowsum blocks interleaved every 3rd bid
// so the heavy role doesn't pile up in the tail wave):
//   bid % 3 == 1 && bid < 768  -> rowsum block (rb = bid/3, 256 of them)
//   otherwise                  -> cross block  (ci = bid - min((bid+2)/3, 256))
// Last block to finish runs the epilogue.
__global__ __launch_bounds__(128) void main_kernel(const float* __restrict__ x,
                                                   float* __restrict__ out) {
    __shared__ union {
        struct {
            u64 v[64][10];          // negated v-pairs [vp][f], padded row (80 B)
            float red[4][NPAIR];    // per-warp cross partials
        } c;
        float row[C_DIM];           // negated full row (rowsum path), 16 KB
        float epi[4][2 * NPAIR + N_F];  // epilogue reduction
    } sh;
    __shared__ bool sh_last;

    const int tid = threadIdx.x;
    const int bid = blockIdx.x;
    const int lane = tid & 31;
    const int warp = tid >> 5;

    const bool is_row = ((bid % 3) == 1) && (bid < 768);

    if (is_row) {
        // ---------------- rowsum: one (f, u) per thread, scalar FADD|abs| ----
        const int rb = bid / 3;           // 0..255
        const int f = rb >> 5;
        const int ut = rb & 31;
        const float* xf = x + f * C_DIM;

        for (int i = tid; i < C_DIM; i += 128) sh.row[i] = -xf[i];

        const int u = ut * 128 + tid;
        const float xu = xf[u];
        __syncthreads();

        float r0 = 0.f, r1 = 0.f, r2 = 0.f, r3 = 0.f;
        const float4* row4 = (const float4*)sh.row;
#pragma unroll 4
        for (int p = 0; p < C_DIM / 4; p++) {
            float4 q = row4[p];
            r0 += fabsf(xu + q.x);
            r1 += fabsf(xu + q.y);
            r2 += fabsf(xu + q.z);
            r3 += fabsf(xu + q.w);
        }
        g_rowsum[f * C_DIM + u] = (r0 + r1) + (r2 + r3);
    } else {
        // ---------------- cross: tile (ti,tj), ti<=tj, packed f32x2 ----------
        int nrb = (bid + 2) / 3; if (nrb > 256) nrb = 256;
        int rem = bid - nrb;              // ci in [0, 528)
        int ti = 0;
        while (rem >= NTILE - ti) { rem -= NTILE - ti; ti++; }
        const int tj = ti + rem;

        // Load negated v-tile as packed pairs: shv[vp][f], coalesced over vp.
        for (int i = tid; i < 64 * N_F; i += 128) {
            int vp = i & 63, f = i >> 6;
            float2 p = *(const float2*)&x[f * C_DIM + tj * 128 + 2 * vp];
            sh.c.v[vp][f] = pack2(-p.x, -p.y);
        }

        const int u = ti * 128 + tid;
        u64 xu2[N_F];
#pragma unroll
        for (int f = 0; f < N_F; f++) {
            float xu = x[f * C_DIM + u];
            xu2[f] = pack2(xu, xu);
        }
        __syncthreads();

        u64 acc2[NPAIR];
#pragma unroll
        for (int k = 0; k < NPAIR; k++) acc2[k] = 0ull;

#pragma unroll 1
        for (int vp = 0; vp < 64; vp++) {
            u64 a2[N_F];
#pragma unroll
            for (int f = 0; f < N_F; f++)
                a2[f] = abs2(add2(xu2[f], sh.c.v[vp][f]));
            int k = 0;
#pragma unroll
            for (int i = 0; i < N_F; i++)
#pragma unroll
                for (int j = i; j < N_F; j++) {
                    acc2[k] = fma2(a2[i], a2[j], acc2[k]);
                    k++;
                }
        }

        // Collapse packed lanes; diagonal tiles weighted 0.5 (self-terms are 0).
        const float w = (ti == tj) ? 0.5f : 1.0f;
        float acc[NPAIR];
#pragma unroll
        for (int k = 0; k < NPAIR; k++) {
            float lo, hi; unpack2(lo, hi, acc2[k]);
            acc[k] = lo + hi;
        }
#pragma unroll
        for (int k = 0; k < NPAIR; k++) {
            float v = acc[k];
            for (int o = 16; o; o >>= 1) v += __shfl_down_sync(0xffffffffu, v, o);
            if (lane == 0) sh.c.red[warp][k] = v * w;
        }
        __syncthreads();
        if (tid < NPAIR) {
            int ci = bid - nrb;
            g_parts[ci][tid] =
                sh.c.red[0][tid] + sh.c.red[1][tid] + sh.c.red[2][tid] + sh.c.red[3][tid];
        }
    }

    // ---------------- completion ticket: last block runs epilogue ------------
    __threadfence();
    if (tid == 0) {
        unsigned old = atomicAdd(&g_ctr, 1);
        sh_last = (old == NBLOCKS - 1);
    }
    __syncthreads();
    if (!sh_last) return;

    // Epilogue (128 threads). Reads bypass L1 (__ldcg) — data written by other SMs.
    float dot[NPAIR], cl[NPAIR], ss[N_F];
#pragma unroll
    for (int k = 0; k < NPAIR; k++) { dot[k] = 0.f; cl[k] = 0.f; }
#pragma unroll
    for (int f = 0; f < N_F; f++) ss[f] = 0.f;

    for (int u = tid; u < C_DIM; u += 128) {
        float r[N_F];
#pragma unroll
        for (int f = 0; f < N_F; f++) {
            r[f] = __ldcg(&g_rowsum[f * C_DIM + u]);
            ss[f] += r[f];
        }
        int k = 0;
#pragma unroll
        for (int i = 0; i < N_F; i++)
#pragma unroll
            for (int j = i; j < N_F; j++) {
                dot[k] = fmaf(r[i], r[j], dot[k]);
                k++;
            }
    }
    for (int b = tid; b < NCROSS; b += 128) {
#pragma unroll
        for (int k = 0; k < NPAIR; k++) cl[k] += __ldcg(&g_parts[b][k]);
    }

#pragma unroll
    for (int k = 0; k < NPAIR; k++) {
        float v = dot[k];
        for (int o = 16; o; o >>= 1) v += __shfl_down_sync(0xffffffffu, v, o);
        if (lane == 0) sh.epi[warp][k] = v;
    }
#pragma unroll
    for (int k = 0; k < NPAIR; k++) {
        float v = cl[k];
        for (int o = 16; o; o >>= 1) v += __shfl_down_sync(0xffffffffu, v, o);
        if (lane == 0) sh.epi[warp][NPAIR + k] = v;
    }
#pragma unroll
    for (int f = 0; f < N_F; f++) {
        float v = ss[f];
        for (int o = 16; o; o >>= 1) v += __shfl_down_sync(0xffffffffu, v, o);
        if (lane == 0) sh.epi[warp][2 * NPAIR + f] = v;
    }
    __syncthreads();

    if (tid == 0) {
        float tot[2 * NPAIR + N_F];
        for (int k = 0; k < 2 * NPAIR + N_F; k++)
            tot[k] = sh.epi[0][k] + sh.epi[1][k] + sh.epi[2][k] + sh.epi[3][k];

        const float fC = (float)C_DIM;
        const float invC2 = 1.0f / (fC * fC);

        float m[N_F];
#pragma unroll
        for (int f = 0; f < N_F; f++) m[f] = tot[2 * NPAIR + f] * invC2;

        // S[i][j] = 2*cross_tri/C^2 - 2*rowdot/C^3 + m_i*m_j
        float dcov[N_F][N_F];
        int k = 0;
        for (int i = 0; i < N_F; i++) {
            for (int j = i; j < N_F; j++) {
                float s = 2.0f * tot[NPAIR + k] * invC2
                        - 2.0f * tot[k] * invC2 / fC
                        + m[i] * m[j];
                float dc = sqrtf(fmaxf(s, 0.0f) + EPS_F);
                dcov[i][j] = dc;
                dcov[j][i] = dc;
                k++;
            }
        }

        float cor = 0.0f;
        for (int i = 0; i < N_F; i++)
            for (int j = i + 1; j < N_F; j++)
                cor += dcov[i][j] / sqrtf(dcov[i][i] * dcov[j][j] + EPS_F);

        out[0] = cor;
        g_ctr = 0;   // reset ticket for graph replay
    }
}

extern "C" void kernel_launch(void* const* d_in, const int* in_sizes, int n_in,
                              void* d_out, int out_size) {
    const float* x = (const float*)d_in[0];
    float* out = (float*)d_out;
    main_kernel<<<NBLOCKS, 128>>>(x, out);
}